// round 17
// baseline (speedup 1.0000x reference)
#include <cuda_runtime.h>
#include <cuda_fp16.h>

#define LL    128
#define NANG  120
#define TB    128
#define ZC    32     // z per thread (single pixel per thread)
#define PY    192    // padded rows in fp16 scratch
#define YOFF  32     // scratch row = image y + YOFF  (y0 in [-27,153] -> yr in [5,186])
#define ABLK  8      // angles per fp16-partial block

typedef unsigned long long u64t;
typedef unsigned int u32t;

// zero-padded fp16 image: [b][a][y+YOFF][z]
__device__ __half g_pad[2][NANG][PY][LL];

__device__ __forceinline__ u64t pack2(float x, float y) {
    u64t r;
    asm("mov.b64 %0, {%1, %2};" : "=l"(r) : "f"(x), "f"(y));
    return r;
}
__device__ __forceinline__ void unpack2(u64t v, float &x, float &y) {
    asm("mov.b64 {%0, %1}, %2;" : "=f"(x), "=f"(y) : "l"(v));
}
__device__ __forceinline__ void fadd2(u64t &acc, u64t v) {
    asm("add.rn.f32x2 %0, %0, %1;" : "+l"(acc) : "l"(v));
}
__device__ __forceinline__ u32t h2_as_u32(__half2 h) {
    return *reinterpret_cast<u32t *>(&h);
}
__device__ __forceinline__ __half2 asH2(u32t v) {
    return *reinterpret_cast<__half2 *>(&v);
}
__device__ __forceinline__ float gfun(float t) {
    return fmaxf(0.0f, fminf(fminf(t + 1.0f, 128.0f - t), 1.0f));
}

// ---------- prep: fp32 image -> zero-padded fp16 scratch ----------
__global__ void prep_kernel(const float * __restrict__ image) {
    int idx = blockIdx.x * blockDim.x + threadIdx.x;   // one uint2 (4 halves) each
    int z4 = idx & 31;                 // LL/4 = 32
    int py = (idx >> 5) % PY;
    int a  = (idx >> 5) / PY % NANG;
    int b  = idx / (32 * PY * NANG);
    if (b >= 2) return;
    int y = py - YOFF;
    uint2 hv = make_uint2(0u, 0u);
    if ((unsigned)y < (unsigned)LL) {
        float4 v = __ldg(reinterpret_cast<const float4 *>(
                             image + (((size_t)b * NANG + a) * LL + y) * LL) + z4);
        hv.x = h2_as_u32(__floats2half2_rn(v.x, v.y));
        hv.y = h2_as_u32(__floats2half2_rn(v.z, v.w));
    }
    *reinterpret_cast<uint2 *>(&g_pad[b][a][py][z4 * 4]) = hv;
}

// ---------- main: no smem staging, no barriers; direct coalesced LDG ----------
__global__ __launch_bounds__(TB, 7)
void bp_kernel(const float * __restrict__ angles, float * __restrict__ out) {
    __shared__ float2 s_tab[NANG];

    const int tid = threadIdx.x;
    if (tid < NANG) {
        float ph = -angles[tid] * 0.017453292519943295f;
        float sv, cv;
        sincosf(ph, &sv, &cv);
        s_tab[tid] = make_float2(cv, sv);
    }

    const int tileX0 = (blockIdx.x & 7) * 16;
    const int tileY0 = (blockIdx.x >> 3) * 8;
    const int z0 = blockIdx.y * ZC;
    const int b  = blockIdx.z;

    const int warp = tid >> 5, lane = tid & 31;
    const int px = tileX0 + (warp & 1) * 8 + (lane & 7);
    const int py = tileY0 + (warp >> 1) * 4 + (lane >> 3);
    const float Xp = px - 63.5f, Yp = py - 63.5f;

    // base pointer for this (b, z0); advances by PY*LL per angle
    const __half *abase = &g_pad[b][0][0][0] + z0;

    u64t acc[16];                      // fp32 packed, 32 z
    #pragma unroll
    for (int i = 0; i < 16; ++i) acc[i] = 0ULL;
    float n1 = 0.0f;

    __syncthreads();  // s_tab ready (only barrier in the kernel)

    for (int blk = 0; blk < NANG / ABLK; ++blk) {
        __half2 pP[16];                // fp16 partials, 32 z
        #pragma unroll
        for (int i = 0; i < 16; ++i) pP[i] = __floats2half2_rn(0.f, 0.f);

        #pragma unroll
        for (int k = 0; k < ABLK; ++k) {
            const int a = blk * ABLK + k;
            const float2 cs = s_tab[a];
            const float c = cs.x, s = cs.y;

            float sx = fmaf(c, Xp, fmaf(s, Yp, 63.5f));
            float sy = fmaf(c, Yp, fmaf(-s, Xp, 63.5f));
            float y0f = floorf(sy);
            float wy  = sy - y0f;

            float hx = gfun(sx);
            n1 = fmaf(hx, gfun(sy), n1);

            float A1 = hx * wy, A0 = hx - A1;     // rows y0, y0+1 (OOB rows are 0)
            __half2 W0 = __float2half2_rn(A0), W1 = __float2half2_rn(A1);

            int yr = (int)y0f + YOFF;             // in [5, 186]
            const uint4 *p0 = reinterpret_cast<const uint4 *>(
                                  abase + ((size_t)a * PY + yr) * LL);
            const uint4 *p1 = reinterpret_cast<const uint4 *>(
                                  abase + ((size_t)a * PY + yr) * LL + LL);

            #pragma unroll
            for (int i = 0; i < 4; ++i) {
                uint4 u = __ldg(p0 + i);          // row y0:   8 halves
                uint4 v = __ldg(p1 + i);          // row y0+1: 8 halves
                pP[4 * i]     = __hfma2(asH2(u.x), W0, pP[4 * i]);
                pP[4 * i + 1] = __hfma2(asH2(u.y), W0, pP[4 * i + 1]);
                pP[4 * i + 2] = __hfma2(asH2(u.z), W0, pP[4 * i + 2]);
                pP[4 * i + 3] = __hfma2(asH2(u.w), W0, pP[4 * i + 3]);
                pP[4 * i]     = __hfma2(asH2(v.x), W1, pP[4 * i]);
                pP[4 * i + 1] = __hfma2(asH2(v.y), W1, pP[4 * i + 1]);
                pP[4 * i + 2] = __hfma2(asH2(v.z), W1, pP[4 * i + 2]);
                pP[4 * i + 3] = __hfma2(asH2(v.w), W1, pP[4 * i + 3]);
            }
        }

        // flush fp16 partials into fp32 packed accumulators
        #pragma unroll
        for (int i = 0; i < 16; ++i) {
            float2 f = __half22float2(pP[i]);
            fadd2(acc[i], pack2(f.x, f.y));
        }
    }

    // epilogue: out = obj / (norm + delta)
    float inv1 = 1.0f / (n1 + 1e-11f);
    float *op = out + (((size_t)b * LL + px) * LL + py) * LL + z0;
    #pragma unroll
    for (int q = 0; q < 8; ++q) {
        float ax, ay, bx, by;
        unpack2(acc[2 * q],     ax, ay);
        unpack2(acc[2 * q + 1], bx, by);
        *reinterpret_cast<float4 *>(op + q * 4) =
            make_float4(ax * inv1, ay * inv1, bx * inv1, by * inv1);
    }
}

extern "C" void kernel_launch(void *const *d_in, const int *in_sizes, int n_in,
                              void *d_out, int out_size) {
    const float *image  = (const float *)d_in[0];
    const float *angles = (const float *)d_in[1];
    float *out = (float *)d_out;

    int total = 2 * NANG * PY * (LL / 4);
    prep_kernel<<<(total + 255) / 256, 256>>>(image);

    dim3 grid(128 /* 8 x-tiles * 16 y-tiles */, LL / ZC /*4*/, 2 /*B*/);
    bp_kernel<<<grid, TB>>>(angles, out);
}